// round 1
// baseline (speedup 1.0000x reference)
#include <cuda_runtime.h>
#include <math.h>

// Problem constants
#define Bdim 2
#define Tdim 2048
#define Cdim 1024
#define Hdim 16
#define Ddim 64
#define Mrows (Bdim * Tdim)   // 4096

// Scratch (device globals: allocation-free, graph-capturable)
__device__ __align__(16) float g_q[(size_t)Bdim * Hdim * Tdim * Ddim];
__device__ __align__(16) float g_k[(size_t)Bdim * Hdim * Tdim * Ddim];
__device__ __align__(16) float g_v[(size_t)Bdim * Hdim * Tdim * Ddim];
__device__ __align__(16) float g_y[(size_t)Bdim * Tdim * Cdim];

// ---------------------------------------------------------------------------
// SGEMM (NT): C[M,N] = A[M,K] @ B[N,K]^T, both row-major (K contiguous).
// 128x128 block tile, BK=16, 256 threads, 8x8 per-thread micro-tile.
// MODE 0: plain row-major store to Cout.
// MODE 1: scatter into g_q/g_k/g_v as [B,H,T,D]; q scaled by 1/sqrt(D).
// A_IS_GY: read A from g_y device global (for GEMM2).
// ---------------------------------------------------------------------------
template <int MODE, bool A_IS_GY>
__global__ void __launch_bounds__(256) sgemm_nt(const float* __restrict__ A,
                                                const float* __restrict__ Bm,
                                                float* __restrict__ Cout,
                                                int M, int N, int K) {
    if (A_IS_GY) A = (const float*)g_y;

    const int bm = blockIdx.y * 128;
    const int bn = blockIdx.x * 128;
    const int tid = threadIdx.x;
    const int tx = tid & 15;   // n micro
    const int ty = tid >> 4;   // m micro

    // transposed smem tiles: [k][m]/[k][n], padded row = 132 floats (16B-aligned)
    __shared__ float As[16 * 132];
    __shared__ float Bs[16 * 132];

    float acc[8][8];
#pragma unroll
    for (int i = 0; i < 8; i++)
#pragma unroll
        for (int j = 0; j < 8; j++) acc[i][j] = 0.f;

    for (int kt = 0; kt < K; kt += 16) {
#pragma unroll
        for (int p = 0; p < 2; p++) {
            int idx = tid + p * 256;        // 0..511
            int row = idx >> 2;             // 0..127
            int c4 = (idx & 3) * 4;         // 0,4,8,12
            float4 va = *(const float4*)&A[(size_t)(bm + row) * K + kt + c4];
            As[(c4 + 0) * 132 + row] = va.x;
            As[(c4 + 1) * 132 + row] = va.y;
            As[(c4 + 2) * 132 + row] = va.z;
            As[(c4 + 3) * 132 + row] = va.w;
            float4 vb = *(const float4*)&Bm[(size_t)(bn + row) * K + kt + c4];
            Bs[(c4 + 0) * 132 + row] = vb.x;
            Bs[(c4 + 1) * 132 + row] = vb.y;
            Bs[(c4 + 2) * 132 + row] = vb.z;
            Bs[(c4 + 3) * 132 + row] = vb.w;
        }
        __syncthreads();

#pragma unroll
        for (int k = 0; k < 16; k++) {
            float4 a0 = *(const float4*)&As[k * 132 + ty * 8];
            float4 a1 = *(const float4*)&As[k * 132 + ty * 8 + 4];
            float4 b0 = *(const float4*)&Bs[k * 132 + tx * 8];
            float4 b1 = *(const float4*)&Bs[k * 132 + tx * 8 + 4];
            float am[8] = {a0.x, a0.y, a0.z, a0.w, a1.x, a1.y, a1.z, a1.w};
            float bn_[8] = {b0.x, b0.y, b0.z, b0.w, b1.x, b1.y, b1.z, b1.w};
#pragma unroll
            for (int ii = 0; ii < 8; ii++)
#pragma unroll
                for (int jj = 0; jj < 8; jj++) acc[ii][jj] += am[ii] * bn_[jj];
        }
        __syncthreads();
    }

    // Epilogue
    if (MODE == 0) {
#pragma unroll
        for (int ii = 0; ii < 8; ii++) {
            int row = bm + ty * 8 + ii;
            int col = bn + tx * 8;
            float4 v0 = make_float4(acc[ii][0], acc[ii][1], acc[ii][2], acc[ii][3]);
            float4 v1 = make_float4(acc[ii][4], acc[ii][5], acc[ii][6], acc[ii][7]);
            *(float4*)&Cout[(size_t)row * N + col] = v0;
            *(float4*)&Cout[(size_t)row * N + col + 4] = v1;
        }
    } else {
#pragma unroll
        for (int ii = 0; ii < 8; ii++) {
            int row = bm + ty * 8 + ii;
            int b = row >> 11;          // /T
            int t = row & (Tdim - 1);
#pragma unroll
            for (int jh = 0; jh < 2; jh++) {
                int j = bn + tx * 8 + jh * 4;
                int s = j >> 10;            // 0=q 1=k 2=v
                int rr = j & (Cdim - 1);
                int h = rr >> 6;
                int d = rr & (Ddim - 1);
                float* dst = (s == 0) ? g_q : (s == 1) ? g_k : g_v;
                float sc = (s == 0) ? 0.125f : 1.0f;   // 1/sqrt(64)
                size_t off = ((size_t)(b * Hdim + h) * Tdim + t) * Ddim + d;
                float4 v = make_float4(acc[ii][jh * 4 + 0] * sc,
                                       acc[ii][jh * 4 + 1] * sc,
                                       acc[ii][jh * 4 + 2] * sc,
                                       acc[ii][jh * 4 + 3] * sc);
                *(float4*)&dst[off] = v;
            }
        }
    }
}

// ---------------------------------------------------------------------------
// Causal flash attention, fp32.
// Grid: (T/128, B*H). 128 threads, 1 q-row per thread.
// K/V tiles 64x64 in smem (warp-uniform broadcast reads), q & O in registers.
// Two-pass online softmax per tile, S staged in padded smem.
// Writes y in [B,T,H,D] (== [B,T,C]) layout for GEMM2.
// ---------------------------------------------------------------------------
__global__ void __launch_bounds__(128) attn_kernel() {
    extern __shared__ float sm[];
    float* Ks = sm;                 // 64*64 = 4096
    float* Vs = sm + 4096;          // 4096
    float* Ss = sm + 8192;          // 128*65 = 8320

    const int tid = threadIdx.x;
    const int bh = blockIdx.y;
    const int q0 = blockIdx.x * 128;
    const int tq = q0 + tid;

    // Stage Q tile (128x64) through smem (reuse Ks+Vs space), then into regs.
    float4* sm4 = (float4*)sm;
    const float4* qg4 = (const float4*)(g_q + ((size_t)bh * Tdim + q0) * Ddim);
    for (int i = tid; i < 128 * 64 / 4; i += 128) sm4[i] = qg4[i];
    __syncthreads();
    float4 q[16];
#pragma unroll
    for (int d4 = 0; d4 < 16; d4++) q[d4] = sm4[tid * 16 + d4];
    __syncthreads();

    float4 o[16];
#pragma unroll
    for (int d4 = 0; d4 < 16; d4++) o[d4] = make_float4(0.f, 0.f, 0.f, 0.f);
    float m = -1e30f, l = 0.f;

    const int ktmax = (q0 + 127) >> 6;   // inclusive
    const float4* Ks4 = (const float4*)Ks;
    const float4* Vs4 = (const float4*)Vs;

    for (int kt = 0; kt <= ktmax; kt++) {
        const float4* kg = (const float4*)(g_k + ((size_t)bh * Tdim + kt * 64) * Ddim);
        const float4* vg = (const float4*)(g_v + ((size_t)bh * Tdim + kt * 64) * Ddim);
#pragma unroll
        for (int p = 0; p < 8; p++) {
            int i = tid + p * 128;
            ((float4*)Ks)[i] = kg[i];
            ((float4*)Vs)[i] = vg[i];
        }
        __syncthreads();

        const bool full = (kt * 64 + 63) <= q0;   // fully unmasked for all rows
        const int kbase = kt * 64;
        float tmax = -1e30f;

        // Pass A: S = q . k, masked, stash in smem, track tile max
        for (int j = 0; j < 64; j++) {
            float s0 = 0.f, s1 = 0.f, s2 = 0.f, s3 = 0.f;
#pragma unroll
            for (int d4 = 0; d4 < 16; d4 += 4) {
                float4 k0 = Ks4[j * 16 + d4 + 0];
                s0 += q[d4 + 0].x * k0.x + q[d4 + 0].y * k0.y + q[d4 + 0].z * k0.z + q[d4 + 0].w * k0.w;
                float4 k1 = Ks4[j * 16 + d4 + 1];
                s1 += q[d4 + 1].x * k1.x + q[d4 + 1].y * k1.y + q[d4 + 1].z * k1.z + q[d4 + 1].w * k1.w;
                float4 k2 = Ks4[j * 16 + d4 + 2];
                s2 += q[d4 + 2].x * k2.x + q[d4 + 2].y * k2.y + q[d4 + 2].z * k2.z + q[d4 + 2].w * k2.w;
                float4 k3 = Ks4[j * 16 + d4 + 3];
                s3 += q[d4 + 3].x * k3.x + q[d4 + 3].y * k3.y + q[d4 + 3].z * k3.z + q[d4 + 3].w * k3.w;
            }
            float s = (s0 + s1) + (s2 + s3);
            if (!full && (kbase + j > tq)) s = -1e30f;
            tmax = fmaxf(tmax, s);
            Ss[tid * 65 + j] = s;
        }

        // Online-softmax rescale
        float mnew = fmaxf(m, tmax);
        float corr = __expf(m - mnew);
        l *= corr;
#pragma unroll
        for (int d4 = 0; d4 < 16; d4++) {
            o[d4].x *= corr; o[d4].y *= corr; o[d4].z *= corr; o[d4].w *= corr;
        }
        m = mnew;

        // Pass B: P = exp(S-m), O += P . V
        for (int j = 0; j < 64; j++) {
            float p = __expf(Ss[tid * 65 + j] - m);
            l += p;
#pragma unroll
            for (int d4 = 0; d4 < 16; d4++) {
                float4 vv = Vs4[j * 16 + d4];
                o[d4].x += p * vv.x; o[d4].y += p * vv.y;
                o[d4].z += p * vv.z; o[d4].w += p * vv.w;
            }
        }
        __syncthreads();
    }

    float inv = 1.0f / l;
    int b = bh >> 4, h = bh & 15;
    float4* yout = (float4*)(g_y + ((size_t)(b * Tdim + tq) * Hdim + h) * Ddim);
#pragma unroll
    for (int d4 = 0; d4 < 16; d4++) {
        yout[d4] = make_float4(o[d4].x * inv, o[d4].y * inv, o[d4].z * inv, o[d4].w * inv);
    }
}

// ---------------------------------------------------------------------------
extern "C" void kernel_launch(void* const* d_in, const int* in_sizes, int n_in,
                              void* d_out, int out_size) {
    const float* x = (const float*)d_in[0];        // [B,T,C]
    const float* w_attn = (const float*)d_in[1];   // [3C,C]
    const float* w_proj = (const float*)d_in[2];   // [C,C]
    float* out = (float*)d_out;                    // [B,T,C]

    const int ATTN_SMEM = (4096 + 4096 + 128 * 65) * 4;  // 66048 B
    cudaFuncSetAttribute(attn_kernel, cudaFuncAttributeMaxDynamicSharedMemorySize,
                         ATTN_SMEM);

    // GEMM1: qkv = x @ w_attn^T, scattered into g_q/g_k/g_v (q pre-scaled)
    dim3 g1(3 * Cdim / 128, Mrows / 128);   // (24, 32)
    sgemm_nt<1, false><<<g1, 256>>>(x, w_attn, nullptr, Mrows, 3 * Cdim, Cdim);

    // Attention
    dim3 ga(Tdim / 128, Bdim * Hdim);       // (16, 32)
    attn_kernel<<<ga, 128, ATTN_SMEM>>>();

    // GEMM2: out = y @ w_proj^T
    dim3 g2(Cdim / 128, Mrows / 128);       // (8, 32)
    sgemm_nt<0, true><<<g2, 256>>>(nullptr, w_proj, out, Mrows, Cdim, Cdim);
}

// round 3
// speedup vs baseline: 1.3845x; 1.3845x over previous
#include <cuda_runtime.h>
#include <cuda_bf16.h>
#include <cstdint>
#include <math.h>

// Problem constants
#define Bdim 2
#define Tdim 2048
#define Cdim 1024
#define Hdim 16
#define Ddim 64
#define Mrows (Bdim * Tdim)   // 4096

// Scratch (device globals: allocation-free, graph-capturable)
__device__ __align__(16) float g_q[(size_t)Bdim * Hdim * Tdim * Ddim];
__device__ __align__(16) float g_k[(size_t)Bdim * Hdim * Tdim * Ddim];
__device__ __align__(16) float g_v[(size_t)Bdim * Hdim * Tdim * Ddim];
__device__ __align__(16) float g_y[(size_t)Bdim * Tdim * Cdim];

// ---------------------------------------------------------------------------
// Helpers
// ---------------------------------------------------------------------------
__device__ __forceinline__ uint32_t smem_u32(const void* p) {
    uint32_t a;
    asm("{ .reg .u64 t; cvta.to.shared.u64 t, %1; cvt.u32.u64 %0, t; }" : "=r"(a) : "l"(p));
    return a;
}

__device__ __forceinline__ void ldsm_x4(uint32_t& r0, uint32_t& r1, uint32_t& r2, uint32_t& r3,
                                        uint32_t addr) {
    asm volatile("ldmatrix.sync.aligned.m8n8.x4.shared.b16 {%0,%1,%2,%3}, [%4];"
                 : "=r"(r0), "=r"(r1), "=r"(r2), "=r"(r3) : "r"(addr));
}

__device__ __forceinline__ void mma16816(float* c, const uint32_t* a, const uint32_t* b) {
    asm volatile(
        "mma.sync.aligned.m16n8k16.row.col.f32.bf16.bf16.f32 "
        "{%0,%1,%2,%3}, {%4,%5,%6,%7}, {%8,%9}, {%0,%1,%2,%3};"
        : "+f"(c[0]), "+f"(c[1]), "+f"(c[2]), "+f"(c[3])
        : "r"(a[0]), "r"(a[1]), "r"(a[2]), "r"(a[3]), "r"(b[0]), "r"(b[1]));
}

__device__ __forceinline__ uint32_t pack2bf16(float x, float y) {
    __nv_bfloat162 t;
    t.x = __float2bfloat16_rn(x);
    t.y = __float2bfloat16_rn(y);
    return *reinterpret_cast<uint32_t*>(&t);
}
__device__ __forceinline__ uint32_t pack2bf16_lo(float x, float y) {
    float hx = __bfloat162float(__float2bfloat16_rn(x));
    float hy = __bfloat162float(__float2bfloat16_rn(y));
    __nv_bfloat162 t;
    t.x = __float2bfloat16_rn(x - hx);
    t.y = __float2bfloat16_rn(y - hy);
    return *reinterpret_cast<uint32_t*>(&t);
}

// ---------------------------------------------------------------------------
// Tensor-core GEMM (NT) via mma.sync bf16, fp32 accuracy via 3-term split.
// C[M,N] = A[M,K] @ B[N,K]^T. 128x128 CTA tile, 256 threads (8 warps 2x4),
// each warp 64x32. K-chunk 32, software pipelined (regs stage next chunk).
// MODE 0: row-major store. MODE 1: scatter to g_q/g_k/g_v [B,H,T,D], q*0.125.
// ---------------------------------------------------------------------------
#define SROW 40   // smem row stride in bf16 (80B: conflict-free ldmatrix)

template <int MODE, bool A_IS_GY>
__global__ void __launch_bounds__(256, 2) gemm_mma(const float* __restrict__ A,
                                                   const float* __restrict__ Bm,
                                                   float* __restrict__ Cout,
                                                   int M, int N, int K) {
    if (A_IS_GY) A = (const float*)g_y;

    __shared__ __align__(16) __nv_bfloat16 sAhi[128 * SROW];
    __shared__ __align__(16) __nv_bfloat16 sAlo[128 * SROW];
    __shared__ __align__(16) __nv_bfloat16 sBhi[128 * SROW];
    __shared__ __align__(16) __nv_bfloat16 sBlo[128 * SROW];

    const int tid = threadIdx.x;
    const int lane = tid & 31;
    const int wid = tid >> 5;
    const int wm = wid >> 2;        // 0..1
    const int wn = wid & 3;         // 0..3
    const int bm = blockIdx.y * 128;
    const int bn = blockIdx.x * 128;

    // Global load mapping: thread covers rows r0+32p (p=0..3), cols c4e..c4e+3
    const int r0 = tid >> 3;
    const int c4e = (tid & 7) * 4;

    const float* Ag = A + (size_t)bm * K;
    const float* Bg = Bm + (size_t)bn * K;

    float4 ra[4], rb[4];
    const int nch = K / 32;

    // prologue: load chunk 0
#pragma unroll
    for (int p = 0; p < 4; p++) {
        ra[p] = *(const float4*)&Ag[(size_t)(r0 + 32 * p) * K + c4e];
        rb[p] = *(const float4*)&Bg[(size_t)(r0 + 32 * p) * K + c4e];
    }

    float acc[4][4][4];
#pragma unroll
    for (int i = 0; i < 4; i++)
#pragma unroll
        for (int j = 0; j < 4; j++)
#pragma unroll
            for (int r = 0; r < 4; r++) acc[i][j][r] = 0.f;

    // ldmatrix shared addresses (bytes)
    const uint32_t aHiB = smem_u32(sAhi), aLoB = smem_u32(sAlo);
    const uint32_t bHiB = smem_u32(sBhi), bLoB = smem_u32(sBlo);
    // A tile: lane -> row (lane&15), k-half (lane>>4)*8
    const uint32_t aOff = (uint32_t)((wm * 64 + (lane & 15)) * SROW + (lane >> 4) * 8) * 2;
    // B tile: lane -> n row (wn*32 + (lane>>4)*8 + (lane&7)), k-half ((lane>>3)&1)*8
    const uint32_t bOff = (uint32_t)((wn * 32 + (lane >> 4) * 8 + (lane & 7)) * SROW +
                                     ((lane >> 3) & 1) * 8) * 2;

    for (int ch = 0; ch < nch; ch++) {
        // store staged chunk to smem (convert to bf16 hi/lo)
#pragma unroll
        for (int p = 0; p < 4; p++) {
            int so = (r0 + 32 * p) * SROW + c4e;
            *(uint2*)&sAhi[so] = make_uint2(pack2bf16(ra[p].x, ra[p].y), pack2bf16(ra[p].z, ra[p].w));
            *(uint2*)&sAlo[so] = make_uint2(pack2bf16_lo(ra[p].x, ra[p].y), pack2bf16_lo(ra[p].z, ra[p].w));
            *(uint2*)&sBhi[so] = make_uint2(pack2bf16(rb[p].x, rb[p].y), pack2bf16(rb[p].z, rb[p].w));
            *(uint2*)&sBlo[so] = make_uint2(pack2bf16_lo(rb[p].x, rb[p].y), pack2bf16_lo(rb[p].z, rb[p].w));
        }
        __syncthreads();

        // prefetch next chunk into regs (LDG latency overlaps compute)
        if (ch + 1 < nch) {
            const float* Ap = Ag + (ch + 1) * 32;
            const float* Bp = Bg + (ch + 1) * 32;
#pragma unroll
            for (int p = 0; p < 4; p++) {
                ra[p] = *(const float4*)&Ap[(size_t)(r0 + 32 * p) * K + c4e];
                rb[p] = *(const float4*)&Bp[(size_t)(r0 + 32 * p) * K + c4e];
            }
        }

        // compute: 2 k-steps of 16
#pragma unroll
        for (int kk = 0; kk < 2; kk++) {
            const uint32_t kByte = (uint32_t)(kk * 16 * 2);
            uint32_t af[4][4];     // A hi, then reused for A lo
            uint32_t bh[4][2], bl[4][2];
#pragma unroll
            for (int i = 0; i < 4; i++)
                ldsm_x4(af[i][0], af[i][1], af[i][2], af[i][3],
                        aHiB + aOff + kByte + (uint32_t)(i * 16 * SROW * 2));
#pragma unroll
            for (int jp = 0; jp < 2; jp++) {
                uint32_t r0_, r1_, r2_, r3_;
                ldsm_x4(r0_, r1_, r2_, r3_, bHiB + bOff + kByte + (uint32_t)(jp * 16 * SROW * 2));
                bh[jp * 2][0] = r0_; bh[jp * 2][1] = r1_;
                bh[jp * 2 + 1][0] = r2_; bh[jp * 2 + 1][1] = r3_;
                ldsm_x4(r0_, r1_, r2_, r3_, bLoB + bOff + kByte + (uint32_t)(jp * 16 * SROW * 2));
                bl[jp * 2][0] = r0_; bl[jp * 2][1] = r1_;
                bl[jp * 2 + 1][0] = r2_; bl[jp * 2 + 1][1] = r3_;
            }
            // hi*hi and hi*lo
#pragma unroll
            for (int i = 0; i < 4; i++)
#pragma unroll
                for (int j = 0; j < 4; j++) {
                    mma16816(acc[i][j], af[i], bh[j]);
                    mma16816(acc[i][j], af[i], bl[j]);
                }
            // lo*hi (reload af with A lo)
#pragma unroll
            for (int i = 0; i < 4; i++)
                ldsm_x4(af[i][0], af[i][1], af[i][2], af[i][3],
                        aLoB + aOff + kByte + (uint32_t)(i * 16 * SROW * 2));
#pragma unroll
            for (int i = 0; i < 4; i++)
#pragma unroll
                for (int j = 0; j < 4; j++)
                    mma16816(acc[i][j], af[i], bh[j]);
        }
        __syncthreads();
    }

    // Epilogue: C frag lane mapping: c0/c1 -> (row l/4, col 2(l%4)+{0,1}),
    //           c2/c3 -> (row l/4+8, same cols)
    const int lr = lane >> 2;
    const int lc = (lane & 3) * 2;

    if (MODE == 0) {
#pragma unroll
        for (int i = 0; i < 4; i++) {
            int rowA = bm + wm * 64 + i * 16 + lr;
#pragma unroll
            for (int j = 0; j < 4; j++) {
                int col = bn + wn * 32 + j * 8 + lc;
                *(float2*)&Cout[(size_t)rowA * N + col] = make_float2(acc[i][j][0], acc[i][j][1]);
                *(float2*)&Cout[(size_t)(rowA + 8) * N + col] = make_float2(acc[i][j][2], acc[i][j][3]);
            }
        }
    } else {
        // whole warp's 32 cols live in one head block
        int col0 = bn + wn * 32;
        int sdx = col0 >> 10;               // 0=q 1=k 2=v
        int rr = col0 & (Cdim - 1);
        int h = rr >> 6;
        int d0 = (rr & (Ddim - 1)) + lc;
        float* dstb = (sdx == 0) ? g_q : (sdx == 1) ? g_k : g_v;
        float sc = (sdx == 0) ? 0.125f : 1.0f;
#pragma unroll
        for (int i = 0; i < 4; i++) {
            int rowA = bm + wm * 64 + i * 16 + lr;
#pragma unroll
            for (int hh = 0; hh < 2; hh++) {
                int row = rowA + hh * 8;
                int b = row >> 11;
                int t = row & (Tdim - 1);
                float* dst = &dstb[((size_t)(b * Hdim + h) * Tdim + t) * Ddim];
#pragma unroll
                for (int j = 0; j < 4; j++) {
                    *(float2*)&dst[d0 + j * 8] =
                        make_float2(acc[i][j][hh * 2] * sc, acc[i][j][hh * 2 + 1] * sc);
                }
            }
        }
    }
}

// ---------------------------------------------------------------------------
// Causal flash attention, fp32 (unchanged; known-good).
// ---------------------------------------------------------------------------
__global__ void __launch_bounds__(128) attn_kernel() {
    extern __shared__ float sm[];
    float* Ks = sm;                 // 64*64 = 4096
    float* Vs = sm + 4096;          // 4096
    float* Ss = sm + 8192;          // 128*65 = 8320

    const int tid = threadIdx.x;
    const int bh = blockIdx.y;
    const int q0 = blockIdx.x * 128;
    const int tq = q0 + tid;

    float4* sm4 = (float4*)sm;
    const float4* qg4 = (const float4*)(g_q + ((size_t)bh * Tdim + q0) * Ddim);
    for (int i = tid; i < 128 * 64 / 4; i += 128) sm4[i] = qg4[i];
    __syncthreads();
    float4 q[16];
#pragma unroll
    for (int d4 = 0; d4 < 16; d4++) q[d4] = sm4[tid * 16 + d4];
    __syncthreads();

    float4 o[16];
#pragma unroll
    for (int d4 = 0; d4 < 16; d4++) o[d4] = make_float4(0.f, 0.f, 0.f, 0.f);
    float m = -1e30f, l = 0.f;

    const int ktmax = (q0 + 127) >> 6;
    const float4* Ks4 = (const float4*)Ks;
    const float4* Vs4 = (const float4*)Vs;

    for (int kt = 0; kt <= ktmax; kt++) {
        const float4* kg = (const float4*)(g_k + ((size_t)bh * Tdim + kt * 64) * Ddim);
        const float4* vg = (const float4*)(g_v + ((size_t)bh * Tdim + kt * 64) * Ddim);
#pragma unroll
        for (int p = 0; p < 8; p++) {
            int i = tid + p * 128;
            ((float4*)Ks)[i] = kg[i];
            ((float4*)Vs)[i] = vg[i];
        }
        __syncthreads();

        const bool full = (kt * 64 + 63) <= q0;
        const int kbase = kt * 64;
        float tmax = -1e30f;

        for (int j = 0; j < 64; j++) {
            float s0 = 0.f, s1 = 0.f, s2 = 0.f, s3 = 0.f;
#pragma unroll
            for (int d4 = 0; d4 < 16; d4 += 4) {
                float4 k0 = Ks4[j * 16 + d4 + 0];
                s0 += q[d4 + 0].x * k0.x + q[d4 + 0].y * k0.y + q[d4 + 0].z * k0.z + q[d4 + 0].w * k0.w;
                float4 k1 = Ks4[j * 16 + d4 + 1];
                s1 += q[d4 + 1].x * k1.x + q[d4 + 1].y * k1.y + q[d4 + 1].z * k1.z + q[d4 + 1].w * k1.w;
                float4 k2 = Ks4[j * 16 + d4 + 2];
                s2 += q[d4 + 2].x * k2.x + q[d4 + 2].y * k2.y + q[d4 + 2].z * k2.z + q[d4 + 2].w * k2.w;
                float4 k3 = Ks4[j * 16 + d4 + 3];
                s3 += q[d4 + 3].x * k3.x + q[d4 + 3].y * k3.y + q[d4 + 3].z * k3.z + q[d4 + 3].w * k3.w;
            }
            float s = (s0 + s1) + (s2 + s3);
            if (!full && (kbase + j > tq)) s = -1e30f;
            tmax = fmaxf(tmax, s);
            Ss[tid * 65 + j] = s;
        }

        float mnew = fmaxf(m, tmax);
        float corr = __expf(m - mnew);
        l *= corr;
#pragma unroll
        for (int d4 = 0; d4 < 16; d4++) {
            o[d4].x *= corr; o[d4].y *= corr; o[d4].z *= corr; o[d4].w *= corr;
        }
        m = mnew;

        for (int j = 0; j < 64; j++) {
            float p = __expf(Ss[tid * 65 + j] - m);
            l += p;
#pragma unroll
            for (int d4 = 0; d4 < 16; d4++) {
                float4 vv = Vs4[j * 16 + d4];
                o[d4].x += p * vv.x; o[d4].y += p * vv.y;
                o[d4].z += p * vv.z; o[d4].w += p * vv.w;
            }
        }
        __syncthreads();
    }

    float inv = 1.0f / l;
    int b = bh >> 4, h = bh & 15;
    float4* yout = (float4*)(g_y + ((size_t)(b * Tdim + tq) * Hdim + h) * Ddim);
#pragma unroll
    for (int d4 = 0; d4 < 16; d4++) {
        yout[d4] = make_float4(o[d4].x * inv, o[d4].y * inv, o[d4].z * inv, o[d4].w * inv);
    }
}

// ---------------------------------------------------------------------------
extern "C" void kernel_launch(void* const* d_in, const int* in_sizes, int n_in,
                              void* d_out, int out_size) {
    const float* x = (const float*)d_in[0];        // [B,T,C]
    const float* w_attn = (const float*)d_in[1];   // [3C,C]
    const float* w_proj = (const float*)d_in[2];   // [C,C]
    float* out = (float*)d_out;                    // [B,T,C]

    const int ATTN_SMEM = (4096 + 4096 + 128 * 65) * 4;  // 66048 B
    cudaFuncSetAttribute(attn_kernel, cudaFuncAttributeMaxDynamicSharedMemorySize, ATTN_SMEM);

    // GEMM1: qkv = x @ w_attn^T -> scattered into g_q/g_k/g_v (q pre-scaled)
    dim3 g1(3 * Cdim / 128, Mrows / 128);   // (24, 32)
    gemm_mma<1, false><<<g1, 256>>>(x, w_attn, nullptr, Mrows, 3 * Cdim, Cdim);

    // Attention
    dim3 ga(Tdim / 128, Bdim * Hdim);       // (16, 32)
    attn_kernel<<<ga, 128, ATTN_SMEM>>>();

    // GEMM2: out = y @ w_proj^T
    dim3 g2(Cdim / 128, Mrows / 128);       // (8, 32)
    gemm_mma<0, true><<<g2, 256>>>(nullptr, w_proj, out, Mrows, Cdim, Cdim);
}

// round 5
// speedup vs baseline: 3.2219x; 2.3270x over previous
#include <cuda_runtime.h>
#include <cuda_bf16.h>
#include <cstdint>
#include <math.h>

// Problem constants
#define Bdim 2
#define Tdim 2048
#define Cdim 1024
#define Hdim 16
#define Ddim 64
#define Mrows (Bdim * Tdim)   // 4096

// Scratch (device globals: allocation-free, graph-capturable)
__device__ __align__(16) float g_q[(size_t)Bdim * Hdim * Tdim * Ddim];
__device__ __align__(16) float g_k[(size_t)Bdim * Hdim * Tdim * Ddim];
__device__ __align__(16) float g_v[(size_t)Bdim * Hdim * Tdim * Ddim];
__device__ __align__(16) float g_y[(size_t)Bdim * Tdim * Cdim];

// ---------------------------------------------------------------------------
// Helpers
// ---------------------------------------------------------------------------
__device__ __forceinline__ uint32_t smem_u32(const void* p) {
    uint32_t a;
    asm("{ .reg .u64 t; cvta.to.shared.u64 t, %1; cvt.u32.u64 %0, t; }" : "=r"(a) : "l"(p));
    return a;
}

__device__ __forceinline__ void ldsm_x4(uint32_t& r0, uint32_t& r1, uint32_t& r2, uint32_t& r3,
                                        uint32_t addr) {
    asm volatile("ldmatrix.sync.aligned.m8n8.x4.shared.b16 {%0,%1,%2,%3}, [%4];"
                 : "=r"(r0), "=r"(r1), "=r"(r2), "=r"(r3) : "r"(addr));
}
__device__ __forceinline__ void ldsm_x4_t(uint32_t& r0, uint32_t& r1, uint32_t& r2, uint32_t& r3,
                                          uint32_t addr) {
    asm volatile("ldmatrix.sync.aligned.m8n8.x4.trans.shared.b16 {%0,%1,%2,%3}, [%4];"
                 : "=r"(r0), "=r"(r1), "=r"(r2), "=r"(r3) : "r"(addr));
}

__device__ __forceinline__ void mma16816(float* c, const uint32_t* a, const uint32_t* b) {
    asm volatile(
        "mma.sync.aligned.m16n8k16.row.col.f32.bf16.bf16.f32 "
        "{%0,%1,%2,%3}, {%4,%5,%6,%7}, {%8,%9}, {%0,%1,%2,%3};"
        : "+f"(c[0]), "+f"(c[1]), "+f"(c[2]), "+f"(c[3])
        : "r"(a[0]), "r"(a[1]), "r"(a[2]), "r"(a[3]), "r"(b[0]), "r"(b[1]));
}

__device__ __forceinline__ uint32_t pack2bf16(float x, float y) {
    __nv_bfloat162 t;
    t.x = __float2bfloat16_rn(x);
    t.y = __float2bfloat16_rn(y);
    return *reinterpret_cast<uint32_t*>(&t);
}
__device__ __forceinline__ uint32_t pack2bf16_lo(float x, float y) {
    float hx = __bfloat162float(__float2bfloat16_rn(x));
    float hy = __bfloat162float(__float2bfloat16_rn(y));
    __nv_bfloat162 t;
    t.x = __float2bfloat16_rn(x - hx);
    t.y = __float2bfloat16_rn(y - hy);
    return *reinterpret_cast<uint32_t*>(&t);
}

#define SROW 40    // GEMM smem row stride in bf16 (32-col chunks; 80B conflict-free)
#define SROWA 72   // Attention smem row stride in bf16 (64-col tiles; 144B conflict-free)

// ---------------------------------------------------------------------------
// Tensor-core GEMM (NT) via mma.sync bf16, fp32 accuracy via 3-term split.
// (unchanged — known good, 268us for GEMM1)
// ---------------------------------------------------------------------------
template <int MODE, bool A_IS_GY>
__global__ void __launch_bounds__(256, 2) gemm_mma(const float* __restrict__ A,
                                                   const float* __restrict__ Bm,
                                                   float* __restrict__ Cout,
                                                   int M, int N, int K) {
    if (A_IS_GY) A = (const float*)g_y;

    __shared__ __align__(16) __nv_bfloat16 sAhi[128 * SROW];
    __shared__ __align__(16) __nv_bfloat16 sAlo[128 * SROW];
    __shared__ __align__(16) __nv_bfloat16 sBhi[128 * SROW];
    __shared__ __align__(16) __nv_bfloat16 sBlo[128 * SROW];

    const int tid = threadIdx.x;
    const int lane = tid & 31;
    const int wid = tid >> 5;
    const int wm = wid >> 2;
    const int wn = wid & 3;
    const int bm = blockIdx.y * 128;
    const int bn = blockIdx.x * 128;

    const int r0 = tid >> 3;
    const int c4e = (tid & 7) * 4;

    const float* Ag = A + (size_t)bm * K;
    const float* Bg = Bm + (size_t)bn * K;

    float4 ra[4], rb[4];
    const int nch = K / 32;

#pragma unroll
    for (int p = 0; p < 4; p++) {
        ra[p] = *(const float4*)&Ag[(size_t)(r0 + 32 * p) * K + c4e];
        rb[p] = *(const float4*)&Bg[(size_t)(r0 + 32 * p) * K + c4e];
    }

    float acc[4][4][4];
#pragma unroll
    for (int i = 0; i < 4; i++)
#pragma unroll
        for (int j = 0; j < 4; j++)
#pragma unroll
            for (int r = 0; r < 4; r++) acc[i][j][r] = 0.f;

    const uint32_t aHiB = smem_u32(sAhi), aLoB = smem_u32(sAlo);
    const uint32_t bHiB = smem_u32(sBhi), bLoB = smem_u32(sBlo);
    const uint32_t aOff = (uint32_t)((wm * 64 + (lane & 15)) * SROW + (lane >> 4) * 8) * 2;
    const uint32_t bOff = (uint32_t)((wn * 32 + (lane >> 4) * 8 + (lane & 7)) * SROW +
                                     ((lane >> 3) & 1) * 8) * 2;

    for (int ch = 0; ch < nch; ch++) {
#pragma unroll
        for (int p = 0; p < 4; p++) {
            int so = (r0 + 32 * p) * SROW + c4e;
            *(uint2*)&sAhi[so] = make_uint2(pack2bf16(ra[p].x, ra[p].y), pack2bf16(ra[p].z, ra[p].w));
            *(uint2*)&sAlo[so] = make_uint2(pack2bf16_lo(ra[p].x, ra[p].y), pack2bf16_lo(ra[p].z, ra[p].w));
            *(uint2*)&sBhi[so] = make_uint2(pack2bf16(rb[p].x, rb[p].y), pack2bf16(rb[p].z, rb[p].w));
            *(uint2*)&sBlo[so] = make_uint2(pack2bf16_lo(rb[p].x, rb[p].y), pack2bf16_lo(rb[p].z, rb[p].w));
        }
        __syncthreads();

        if (ch + 1 < nch) {
            const float* Ap = Ag + (ch + 1) * 32;
            const float* Bp = Bg + (ch + 1) * 32;
#pragma unroll
            for (int p = 0; p < 4; p++) {
                ra[p] = *(const float4*)&Ap[(size_t)(r0 + 32 * p) * K + c4e];
                rb[p] = *(const float4*)&Bp[(size_t)(r0 + 32 * p) * K + c4e];
            }
        }

#pragma unroll
        for (int kk = 0; kk < 2; kk++) {
            const uint32_t kByte = (uint32_t)(kk * 16 * 2);
            uint32_t af[4][4];
            uint32_t bh[4][2], bl[4][2];
#pragma unroll
            for (int i = 0; i < 4; i++)
                ldsm_x4(af[i][0], af[i][1], af[i][2], af[i][3],
                        aHiB + aOff + kByte + (uint32_t)(i * 16 * SROW * 2));
#pragma unroll
            for (int jp = 0; jp < 2; jp++) {
                uint32_t r0_, r1_, r2_, r3_;
                ldsm_x4(r0_, r1_, r2_, r3_, bHiB + bOff + kByte + (uint32_t)(jp * 16 * SROW * 2));
                bh[jp * 2][0] = r0_; bh[jp * 2][1] = r1_;
                bh[jp * 2 + 1][0] = r2_; bh[jp * 2 + 1][1] = r3_;
                ldsm_x4(r0_, r1_, r2_, r3_, bLoB + bOff + kByte + (uint32_t)(jp * 16 * SROW * 2));
                bl[jp * 2][0] = r0_; bl[jp * 2][1] = r1_;
                bl[jp * 2 + 1][0] = r2_; bl[jp * 2 + 1][1] = r3_;
            }
#pragma unroll
            for (int i = 0; i < 4; i++)
#pragma unroll
                for (int j = 0; j < 4; j++) {
                    mma16816(acc[i][j], af[i], bh[j]);
                    mma16816(acc[i][j], af[i], bl[j]);
                }
#pragma unroll
            for (int i = 0; i < 4; i++)
                ldsm_x4(af[i][0], af[i][1], af[i][2], af[i][3],
                        aLoB + aOff + kByte + (uint32_t)(i * 16 * SROW * 2));
#pragma unroll
            for (int i = 0; i < 4; i++)
#pragma unroll
                for (int j = 0; j < 4; j++)
                    mma16816(acc[i][j], af[i], bh[j]);
        }
        __syncthreads();
    }

    const int lr = lane >> 2;
    const int lc = (lane & 3) * 2;

    if (MODE == 0) {
#pragma unroll
        for (int i = 0; i < 4; i++) {
            int rowA = bm + wm * 64 + i * 16 + lr;
#pragma unroll
            for (int j = 0; j < 4; j++) {
                int col = bn + wn * 32 + j * 8 + lc;
                *(float2*)&Cout[(size_t)rowA * N + col] = make_float2(acc[i][j][0], acc[i][j][1]);
                *(float2*)&Cout[(size_t)(rowA + 8) * N + col] = make_float2(acc[i][j][2], acc[i][j][3]);
            }
        }
    } else {
        int col0 = bn + wn * 32;
        int sdx = col0 >> 10;
        int rr = col0 & (Cdim - 1);
        int h = rr >> 6;
        int d0 = (rr & (Ddim - 1)) + lc;
        float* dstb = (sdx == 0) ? g_q : (sdx == 1) ? g_k : g_v;
        float sc = (sdx == 0) ? 0.125f : 1.0f;
#pragma unroll
        for (int i = 0; i < 4; i++) {
            int rowA = bm + wm * 64 + i * 16 + lr;
#pragma unroll
            for (int hh = 0; hh < 2; hh++) {
                int row = rowA + hh * 8;
                int b = row >> 11;
                int t = row & (Tdim - 1);
                float* dst = &dstb[((size_t)(b * Hdim + h) * Tdim + t) * Ddim];
#pragma unroll
                for (int j = 0; j < 4; j++) {
                    *(float2*)&dst[d0 + j * 8] =
                        make_float2(acc[i][j][hh * 2] * sc, acc[i][j][hh * 2 + 1] * sc);
                }
            }
        }
    }
}

// ---------------------------------------------------------------------------
// Tensor-core causal flash attention (mma.sync bf16, 3-term splits).
// Grid: (T/128, B*H), 256 threads. Warp w owns q-rows [16w,16w+16).
// K tiles of 64 rows, D=64 cols, smem row stride SROWA=72 bf16.
// ---------------------------------------------------------------------------
__global__ void __launch_bounds__(256, 1) attn_mma() {
    // K/V tiles: 64*72*2 = 9216 B each; Q staging overlay: 2 x 128*72*2 = 36864 B
    __shared__ __align__(16) char sbuf[36864];
    const uint32_t sb = smem_u32(sbuf);
    const int tid = threadIdx.x;
    const int lane = tid & 31;
    const int w = tid >> 5;
    const int bh = blockIdx.y;
    const int q0 = (int)(gridDim.x - 1 - blockIdx.x) * 128;   // heavy tiles first

    const float* Qg = g_q + ((size_t)bh * Tdim + q0) * Ddim;
    const float* Kg = g_k + (size_t)bh * Tdim * Ddim;
    const float* Vg = g_v + (size_t)bh * Tdim * Ddim;

    // smem offsets (bytes)
    const uint32_t oKhi = 0, oKlo = 9216, oVhi = 18432, oVlo = 27648;
    const uint32_t oQhi = 0, oQlo = 18432;   // staging overlay (before main loop)

    // ---- stage Q (128x64) hi/lo, load A-fragments ----
#pragma unroll
    for (int p = 0; p < 8; p++) {
        int idx = p * 256 + tid;
        int row = idx >> 4;
        int c4 = (idx & 15) * 4;
        float4 v = *(const float4*)&Qg[(size_t)row * Ddim + c4];
        uint32_t so = (uint32_t)(row * SROWA + c4) * 2;
        *(uint2*)(sbuf + oQhi + so) = make_uint2(pack2bf16(v.x, v.y), pack2bf16(v.z, v.w));
        *(uint2*)(sbuf + oQlo + so) = make_uint2(pack2bf16_lo(v.x, v.y), pack2bf16_lo(v.z, v.w));
    }
    __syncthreads();

    uint32_t qh[4][4], ql[4][4];
#pragma unroll
    for (int kk = 0; kk < 4; kk++) {
        uint32_t off = (uint32_t)((16 * w + (lane & 15)) * SROWA + 16 * kk + 8 * (lane >> 4)) * 2;
        ldsm_x4(qh[kk][0], qh[kk][1], qh[kk][2], qh[kk][3], sb + oQhi + off);
        ldsm_x4(ql[kk][0], ql[kk][1], ql[kk][2], ql[kk][3], sb + oQlo + off);
    }
    __syncthreads();

    // state
    float oacc[8][4];
#pragma unroll
    for (int j = 0; j < 8; j++)
#pragma unroll
        for (int r = 0; r < 4; r++) oacc[j][r] = 0.f;
    float m1 = -1e30f, m2 = -1e30f, l1 = 0.f, l2 = 0.f;

    const int r1 = q0 + 16 * w + (lane >> 2);
    const int r2 = r1 + 8;
    const int ktmax = (q0 + 127) >> 6;

    // prologue prefetch kt=0
    float4 kreg[4], vreg[4];
#pragma unroll
    for (int p = 0; p < 4; p++) {
        int idx = p * 256 + tid;
        int row = idx >> 4;
        int c4 = (idx & 15) * 4;
        kreg[p] = *(const float4*)&Kg[(size_t)row * Ddim + c4];
        vreg[p] = *(const float4*)&Vg[(size_t)row * Ddim + c4];
    }

    for (int kt = 0; kt <= ktmax; kt++) {
        const int kbase = kt * 64;

        // store staged K/V tile hi/lo
#pragma unroll
        for (int p = 0; p < 4; p++) {
            int idx = p * 256 + tid;
            int row = idx >> 4;
            int c4 = (idx & 15) * 4;
            uint32_t so = (uint32_t)(row * SROWA + c4) * 2;
            *(uint2*)(sbuf + oKhi + so) = make_uint2(pack2bf16(kreg[p].x, kreg[p].y), pack2bf16(kreg[p].z, kreg[p].w));
            *(uint2*)(sbuf + oKlo + so) = make_uint2(pack2bf16_lo(kreg[p].x, kreg[p].y), pack2bf16_lo(kreg[p].z, kreg[p].w));
            *(uint2*)(sbuf + oVhi + so) = make_uint2(pack2bf16(vreg[p].x, vreg[p].y), pack2bf16(vreg[p].z, vreg[p].w));
            *(uint2*)(sbuf + oVlo + so) = make_uint2(pack2bf16_lo(vreg[p].x, vreg[p].y), pack2bf16_lo(vreg[p].z, vreg[p].w));
        }
        __syncthreads();

        // prefetch next tile
        if (kt < ktmax) {
            const float* Kp = Kg + (size_t)(kbase + 64) * Ddim;
            const float* Vp = Vg + (size_t)(kbase + 64) * Ddim;
#pragma unroll
            for (int p = 0; p < 4; p++) {
                int idx = p * 256 + tid;
                int row = idx >> 4;
                int c4 = (idx & 15) * 4;
                kreg[p] = *(const float4*)&Kp[(size_t)row * Ddim + c4];
                vreg[p] = *(const float4*)&Vp[(size_t)row * Ddim + c4];
            }
        }

        // ---- S = Q.K^T (3-term) ----
        float sacc[8][4];
#pragma unroll
        for (int j = 0; j < 8; j++)
#pragma unroll
            for (int r = 0; r < 4; r++) sacc[j][r] = 0.f;

#pragma unroll
        for (int kk = 0; kk < 4; kk++) {
            uint32_t bhp[8][2], blp[8][2];
#pragma unroll
            for (int np = 0; np < 4; np++) {
                uint32_t off = (uint32_t)((np * 16 + (lane >> 4) * 8 + (lane & 7)) * SROWA +
                                          ((lane >> 3) & 1) * 8 + 16 * kk) * 2;
                uint32_t t0, t1, t2, t3;
                ldsm_x4(t0, t1, t2, t3, sb + oKhi + off);
                bhp[2 * np][0] = t0; bhp[2 * np][1] = t1;
                bhp[2 * np + 1][0] = t2; bhp[2 * np + 1][1] = t3;
                ldsm_x4(t0, t1, t2, t3, sb + oKlo + off);
                blp[2 * np][0] = t0; blp[2 * np][1] = t1;
                blp[2 * np + 1][0] = t2; blp[2 * np + 1][1] = t3;
            }
#pragma unroll
            for (int j = 0; j < 8; j++) {
                mma16816(sacc[j], qh[kk], bhp[j]);
                mma16816(sacc[j], qh[kk], blp[j]);
                mma16816(sacc[j], ql[kk], bhp[j]);
            }
        }

        // ---- causal mask (diagonal tiles only; warp-uniform branch) ----
        if (kbase + 63 > q0 + 16 * w) {
            const int c0 = kbase + 2 * (lane & 3);
#pragma unroll
            for (int j = 0; j < 8; j++) {
                int cj = c0 + 8 * j;
                if (cj > r1)     sacc[j][0] = -1e30f;
                if (cj + 1 > r1) sacc[j][1] = -1e30f;
                if (cj > r2)     sacc[j][2] = -1e30f;
                if (cj + 1 > r2) sacc[j][3] = -1e30f;
            }
        }

        // ---- online softmax ----
        float t1m = -1e30f, t2m = -1e30f;
#pragma unroll
        for (int j = 0; j < 8; j++) {
            t1m = fmaxf(t1m, fmaxf(sacc[j][0], sacc[j][1]));
            t2m = fmaxf(t2m, fmaxf(sacc[j][2], sacc[j][3]));
        }
        t1m = fmaxf(t1m, __shfl_xor_sync(0xffffffffu, t1m, 1));
        t1m = fmaxf(t1m, __shfl_xor_sync(0xffffffffu, t1m, 2));
        t2m = fmaxf(t2m, __shfl_xor_sync(0xffffffffu, t2m, 1));
        t2m = fmaxf(t2m, __shfl_xor_sync(0xffffffffu, t2m, 2));

        float nm1 = fmaxf(m1, t1m), nm2 = fmaxf(m2, t2m);
        float corr1 = __expf(m1 - nm1), corr2 = __expf(m2 - nm2);
        m1 = nm1; m2 = nm2;

        float s1 = 0.f, s2 = 0.f;
#pragma unroll
        for (int j = 0; j < 8; j++) {
            sacc[j][0] = __expf(sacc[j][0] - m1);
            sacc[j][1] = __expf(sacc[j][1] - m1);
            sacc[j][2] = __expf(sacc[j][2] - m2);
            sacc[j][3] = __expf(sacc[j][3] - m2);
            s1 += sacc[j][0] + sacc[j][1];
            s2 += sacc[j][2] + sacc[j][3];
        }
        s1 += __shfl_xor_sync(0xffffffffu, s1, 1);
        s1 += __shfl_xor_sync(0xffffffffu, s1, 2);
        s2 += __shfl_xor_sync(0xffffffffu, s2, 1);
        s2 += __shfl_xor_sync(0xffffffffu, s2, 2);
        l1 = l1 * corr1 + s1;
        l2 = l2 * corr2 + s2;

        // pack P into A-fragments (hi/lo)
        uint32_t ph[4][4], pl[4][4];
#pragma unroll
        for (int kk = 0; kk < 4; kk++) {
            int j0 = 2 * kk, j1 = 2 * kk + 1;
            ph[kk][0] = pack2bf16(sacc[j0][0], sacc[j0][1]);
            ph[kk][1] = pack2bf16(sacc[j0][2], sacc[j0][3]);
            ph[kk][2] = pack2bf16(sacc[j1][0], sacc[j1][1]);
            ph[kk][3] = pack2bf16(sacc[j1][2], sacc[j1][3]);
            pl[kk][0] = pack2bf16_lo(sacc[j0][0], sacc[j0][1]);
            pl[kk][1] = pack2bf16_lo(sacc[j0][2], sacc[j0][3]);
            pl[kk][2] = pack2bf16_lo(sacc[j1][0], sacc[j1][1]);
            pl[kk][3] = pack2bf16_lo(sacc[j1][2], sacc[j1][3]);
        }

        // rescale O
#pragma unroll
        for (int j = 0; j < 8; j++) {
            oacc[j][0] *= corr1; oacc[j][1] *= corr1;
            oacc[j][2] *= corr2; oacc[j][3] *= corr2;
        }

        // ---- O += P.V (3-term; V via ldmatrix.trans) ----
#pragma unroll
        for (int kk = 0; kk < 4; kk++) {
            uint32_t vbh[8][2], vbl[8][2];
#pragma unroll
            for (int np = 0; np < 4; np++) {
                uint32_t off = (uint32_t)((16 * kk + (lane & 15)) * SROWA +
                                          16 * np + 8 * (lane >> 4)) * 2;
                uint32_t t0, t1, t2, t3;
                ldsm_x4_t(t0, t1, t2, t3, sb + oVhi + off);
                vbh[2 * np][0] = t0; vbh[2 * np][1] = t1;
                vbh[2 * np + 1][0] = t2; vbh[2 * np + 1][1] = t3;
                ldsm_x4_t(t0, t1, t2, t3, sb + oVlo + off);
                vbl[2 * np][0] = t0; vbl[2 * np][1] = t1;
                vbl[2 * np + 1][0] = t2; vbl[2 * np + 1][1] = t3;
            }
#pragma unroll
            for (int j = 0; j < 8; j++) {
                mma16816(oacc[j], ph[kk], vbh[j]);
                mma16816(oacc[j], ph[kk], vbl[j]);
                mma16816(oacc[j], pl[kk], vbh[j]);
            }
        }
        __syncthreads();
    }

    // ---- epilogue: y[B,T,H,D] ----
    float inv1 = 1.0f / l1, inv2 = 1.0f / l2;
    int b = bh >> 4, h = bh & 15;
    float* y1 = g_y + ((size_t)(b * Tdim + r1) * Hdim + h) * Ddim;
    float* y2 = g_y + ((size_t)(b * Tdim + r2) * Hdim + h) * Ddim;
    int d0 = 2 * (lane & 3);
#pragma unroll
    for (int j = 0; j < 8; j++) {
        *(float2*)&y1[8 * j + d0] = make_float2(oacc[j][0] * inv1, oacc[j][1] * inv1);
        *(float2*)&y2[8 * j + d0] = make_float2(oacc[j][2] * inv2, oacc[j][3] * inv2);
    }
}

// ---------------------------------------------------------------------------
extern "C" void kernel_launch(void* const* d_in, const int* in_sizes, int n_in,
                              void* d_out, int out_size) {
    const float* x = (const float*)d_in[0];        // [B,T,C]
    const float* w_attn = (const float*)d_in[1];   // [3C,C]
    const float* w_proj = (const float*)d_in[2];   // [C,C]
    float* out = (float*)d_out;                    // [B,T,C]

    // GEMM1: qkv = x @ w_attn^T -> scattered into g_q/g_k/g_v (q pre-scaled)
    dim3 g1(3 * Cdim / 128, Mrows / 128);   // (24, 32)
    gemm_mma<1, false><<<g1, 256>>>(x, w_attn, nullptr, Mrows, 3 * Cdim, Cdim);

    // Attention (tensor cores)
    dim3 ga(Tdim / 128, Bdim * Hdim);       // (16, 32)
    attn_mma<<<ga, 256>>>();

    // GEMM2: out = y @ w_proj^T
    dim3 g2(Cdim / 128, Mrows / 128);       // (8, 32)
    gemm_mma<0, true><<<g2, 256>>>(nullptr, w_proj, out, Mrows, Cdim, Cdim);
}